// round 17
// baseline (speedup 1.0000x reference)
#include <cuda_runtime.h>
#include <cuda_fp16.h>
#include <cuda_fp8.h>
#include <math.h>
#include <stdint.h>

#define NN   262144
#define EE   2097152
#define HID  200
#define MT   128                 // rows per CTA
#define CAC  240                 // A smem row stride BYTES; 16-aligned (ldmatrix!), conflict-free
#define NCHK 7                   // k chunks of 32 (224 >= 200, zero padded)
#define NG   (6 * NCHK)          // 42 global chunks across layers 1..6
#define BNR  216                 // B rows (n, padded)
#define BKP  48                  // B row stride bytes (32 k + 16 pad); 16-aligned
#define SA_PLANE (MT * CAC)              // 30720 B (fp8 A plane)
#define SM_A     0
#define SM_B     SA_PLANE
#define BUFSZ    (BNR * BKP)             // 10368 B per chunk
#define NBUF     4                       // ring of 4 B buffers, prefetch depth 2
#define SMEM_BYTES (SM_B + NBUF * BUFSZ) // 72192
#define THREADS  256

#define WSCALE 16.0f
#define ASCALE 8.0f
#define OSCALE (1.0f / (WSCALE * ASCALE))

// ------------------------- device globals (scratch) -------------------------
__device__ float g_deg[NN];
__device__ float g_inv[NN];
__device__ float g_agg[NN];
__device__ int   g_is64;
// weights as fp8 e4m3 (x16), pre-transposed [layer][chunk][n(216)][k(48 pad)]
__device__ __align__(16) unsigned char g_wt8[6][NCHK][BNR][BKP];

struct Params {
    const float* W[8];
    const float* b[8];
};

// ------------------------------- PTX helpers --------------------------------
__device__ __forceinline__ uint32_t smem_u32(const void* p) {
    uint32_t a;
    asm("{ .reg .u64 t; cvta.to.shared.u64 t, %1; cvt.u32.u64 %0, t; }" : "=r"(a) : "l"(p));
    return a;
}
__device__ __forceinline__ void cp16(uint32_t sdst, const void* gsrc) {
    asm volatile("cp.async.cg.shared.global [%0], [%1], 16;" :: "r"(sdst), "l"(gsrc));
}
#define CP_COMMIT() asm volatile("cp.async.commit_group;")
#define CP_WAIT1()  asm volatile("cp.async.wait_group 1;")
#define CP_WAIT0()  asm volatile("cp.async.wait_group 0;")

__device__ __forceinline__ void ldsm_x4(uint32_t* r, uint32_t addr) {
    asm volatile("ldmatrix.sync.aligned.m8n8.x4.shared.b16 {%0,%1,%2,%3}, [%4];"
                 : "=r"(r[0]), "=r"(r[1]), "=r"(r[2]), "=r"(r[3]) : "r"(addr));
}
__device__ __forceinline__ void ldsm_x2(uint32_t* r, uint32_t addr) {
    asm volatile("ldmatrix.sync.aligned.m8n8.x2.shared.b16 {%0,%1}, [%2];"
                 : "=r"(r[0]), "=r"(r[1]) : "r"(addr));
}
// fp8 e4m3 MMA, K=32 per instruction
__device__ __forceinline__ void mma_fp8(float* d, const uint32_t* a, uint32_t b0, uint32_t b1) {
    asm volatile(
        "mma.sync.aligned.m16n8k32.row.col.f32.e4m3.e4m3.f32 "
        "{%0,%1,%2,%3}, {%4,%5,%6,%7}, {%8,%9}, {%0,%1,%2,%3};"
        : "+f"(d[0]), "+f"(d[1]), "+f"(d[2]), "+f"(d[3])
        : "r"(a[0]), "r"(a[1]), "r"(a[2]), "r"(a[3]), "r"(b0), "r"(b1));
}

__device__ __forceinline__ unsigned char to_fp8(float v) {
    return (unsigned char)__nv_cvt_float_to_fp8(v, __NV_SATFINITE, __NV_E4M3);
}

// ------------------------- edge aggregation kernels -------------------------
__global__ void detect_kernel(const int* __restrict__ ei32) {
    if (blockIdx.x == 0 && threadIdx.x == 0) {
        int orv = 0;
        for (int i = 1; i < 128; i += 2) orv |= ei32[i];
        g_is64 = (orv == 0) ? 1 : 0;
    }
}
__device__ __forceinline__ int load_idx(const void* ei, long long pos, int is64) {
    if (is64) return (int)((const long long*)ei)[pos];
    return ((const int*)ei)[pos];
}
__global__ void zero_deg_kernel() {
    int i = blockIdx.x * blockDim.x + threadIdx.x;
    if (i < NN) g_deg[i] = 0.0f;
}
__global__ void deg_kernel(const void* __restrict__ ei) {
    const int is64 = g_is64;
    long long stride = (long long)gridDim.x * blockDim.x;
    for (long long e = (long long)blockIdx.x * blockDim.x + threadIdx.x; e < EE; e += stride) {
        int d = load_idx(ei, (long long)EE + e, is64);
        atomicAdd(&g_deg[d], 1.0f);
    }
}
__global__ void inv_init_kernel(const float* __restrict__ x) {
    int i = blockIdx.x * blockDim.x + threadIdx.x;
    if (i < NN) {
        float inv = rsqrtf(g_deg[i] + 1.0f);
        g_inv[i] = inv;
        g_agg[i] = x[i] * inv * inv;
    }
}
__global__ void edge_agg_kernel(const float* __restrict__ x, const void* __restrict__ ei) {
    const int is64 = g_is64;
    long long stride = (long long)gridDim.x * blockDim.x;
    for (long long e = (long long)blockIdx.x * blockDim.x + threadIdx.x; e < EE; e += stride) {
        int s = load_idx(ei, e, is64);
        int d = load_idx(ei, (long long)EE + e, is64);
        atomicAdd(&g_agg[d], x[s] * g_inv[s] * g_inv[d]);
    }
}

// ---------- weight prep: fp32 -> fp8 e4m3 (x16), transposed [n][k] ----------
__global__ void prep_w_kernel(Params p) {
    int idx = blockIdx.x * blockDim.x + threadIdx.x;
    const int total = 6 * NCHK * BNR * BKP;
    if (idx >= total) return;
    int kb = idx % BKP;                 // byte within row (0..47)
    int n  = (idx / BKP) % BNR;
    int c  = (idx / (BKP * BNR)) % NCHK;
    int l  = idx / (BKP * BNR * NCHK);
    unsigned char v8 = 0;
    if (kb < 32 && n < HID) {
        int kg = c * 32 + kb;
        if (kg < HID) v8 = to_fp8(p.W[l + 1][kg * HID + n] * WSCALE);
    }
    g_wt8[l][c][n][kb] = v8;
}

// ------------------------------ fused MLP kernel ----------------------------
__device__ __forceinline__ void a_store(char* sm, int r, int j, float v0, float v1) {
    // store 2 fp8 bytes (activations scaled by ASCALE)
    uint16_t pk = (uint16_t)to_fp8(v0) | ((uint16_t)to_fp8(v1) << 8);
    *(uint16_t*)(sm + SM_A + r * CAC + j) = pk;
}

__global__ void __launch_bounds__(THREADS, 1) mlp_kernel(Params p, float* __restrict__ out) {
    extern __shared__ char sm[];
    const uint32_t sbase = smem_u32(sm);
    const int tid  = threadIdx.x;
    const int wid  = tid >> 5;
    const int lane = tid & 31;
    const int wr   = wid & 3;       // row group: rows 32*wr..+31 (two m16 subtiles)
    const int wc   = wid >> 2;      // col half: cols 104*wc..+103
    const int row0 = blockIdx.x * MT;

    // ldmatrix lane address components (fp8 tiles, byte offsets; all 16B aligned)
    const int rl   = lane & 7;
    const int arow = rl + 8 * ((lane >> 3) & 1);
    const int acol = 16 * (lane >> 4);
    const uint32_t aP0 = sbase + SM_A + (wr * 32 + arow) * CAC + acol;   // rows 0-15 of warp block
    const uint32_t aP1 = aP0 + 16 * CAC;                                  // rows 16-31
    // B x4: quad0: n rl k0-15; quad1: n rl k16-31; quad2: n rl+8 k0; quad3: n rl+8 k16
    const int quad = lane >> 3;
    const uint32_t bOff  = (uint32_t)((rl + 8 * (quad >> 1)) * BKP + (quad & 1) * 16);
    // B x2 (tile12): lanes0-7: n rl k0-15; lanes8-15: n rl k16-31
    const uint32_t b2Off = (uint32_t)(rl * BKP + ((lane >> 3) & 1) * 16);

    const char* wflat = (const char*)&g_wt8[0][0][0][0];

    // stage chunks 0 and 1 into ring slots 0,1 (overlaps layer-0 gather)
    for (int i = tid * 16; i < BUFSZ; i += THREADS * 16)
        cp16(sbase + SM_B + i, wflat + i);
    CP_COMMIT();
    for (int i = tid * 16; i < BUFSZ; i += THREADS * 16)
        cp16(sbase + SM_B + BUFSZ + i, wflat + BUFSZ + i);
    CP_COMMIT();

    // ---- layer 0: A = relu(agg * W0 + b0) * ASCALE -> fp8, zero pad k>=200 ----
    {
        const float* W0 = p.W[0];
        const float* b0 = p.b[0];
        for (int idx = tid; idx < MT * 112; idx += THREADS) {   // 224 bytes / 2
            int r = idx / 112;
            int j = (idx - r * 112) * 2;
            float agg = g_agg[row0 + r];
            float v0 = (j < HID)     ? fmaxf(fmaf(agg, W0[j],     b0[j]),     0.0f) : 0.0f;
            float v1 = (j + 1 < HID) ? fmaxf(fmaf(agg, W0[j + 1], b0[j + 1]), 0.0f) : 0.0f;
            a_store(sm, r, j, v0 * ASCALE, v1 * ASCALE);
        }
    }
    __syncthreads();   // cross-warp A writes of layer 0

    for (int l = 1; l <= 6; ++l) {
        float acc[2][13][4];
        #pragma unroll
        for (int s = 0; s < 2; ++s)
            #pragma unroll
            for (int t = 0; t < 13; ++t)
                #pragma unroll
                for (int q = 0; q < 4; ++q) acc[s][t][q] = 0.0f;
        float acc12[4] = {0.0f, 0.0f, 0.0f, 0.0f};   // tile 12 (rows subtile = wc)

        for (int c = 0; c < NCHK; ++c) {
            const int g = (l - 1) * NCHK + c;           // global chunk id
            if (g < NG - 1) { CP_WAIT1(); } else { CP_WAIT0(); }
            __syncthreads();   // chunk g visible; all reads of slot (g+2)&3 done

            if (g + 2 < NG) {  // stage chunk g+2 into ring slot (g+2)&3
                const char* src = wflat + (size_t)(g + 2) * BUFSZ;
                uint32_t dst = sbase + SM_B + ((g + 2) & (NBUF - 1)) * BUFSZ;
                for (int i = tid * 16; i < BUFSZ; i += THREADS * 16)
                    cp16(dst + i, src + i);
                CP_COMMIT();
            }

            const uint32_t curB = sbase + SM_B + (g & (NBUF - 1)) * BUFSZ;
            const int kb = c * 32;   // byte offset in A row
            uint32_t a0[4], a1[4];
            ldsm_x4(a0, aP0 + kb);   // warp rows 0-15, k32
            ldsm_x4(a1, aP1 + kb);   // warp rows 16-31, k32
            #pragma unroll
            for (int pr = 0; pr < 6; ++pr) {
                const int nc = wc * 104 + pr * 16;
                uint32_t bh[4];
                ldsm_x4(bh, curB + nc * BKP + bOff);   // n16 x k32
                mma_fp8(acc[0][2 * pr],     a0, bh[0], bh[1]);
                mma_fp8(acc[0][2 * pr + 1], a0, bh[2], bh[3]);
                mma_fp8(acc[1][2 * pr],     a1, bh[0], bh[1]);
                mma_fp8(acc[1][2 * pr + 1], a1, bh[2], bh[3]);
            }
            // tile 12 (global cols 96..103): wc0 -> row subtile 0, wc1 -> subtile 1.
            {
                uint32_t bh2[2];
                ldsm_x2(bh2, curB + 96 * BKP + b2Off);
                if (wc == 0) {
                    mma_fp8(acc12, a0, bh2[0], bh2[1]);
                } else {
                    mma_fp8(acc12, a1, bh2[0], bh2[1]);
                }
            }
            // no trailing barrier (ring depth 4; next chunk's barrier orders reuse)
        }

        if (l < 6) {
            // epilogue: scale + bias + relu -> fp8 back into A (own rows only)
            const float* bias = p.b[l];
            #pragma unroll
            for (int s = 0; s < 2; ++s) {
                const int r0 = wr * 32 + s * 16 + (lane >> 2);
                const int r1 = r0 + 8;
                #pragma unroll
                for (int t = 0; t < 12; ++t) {   // j, j+1 always < 200
                    int j = wc * 104 + t * 8 + 2 * (lane & 3);
                    float bj0 = bias[j], bj1 = bias[j + 1];
                    a_store(sm, r0, j,
                            fmaxf(fmaf(acc[s][t][0], OSCALE, bj0), 0.0f) * ASCALE,
                            fmaxf(fmaf(acc[s][t][1], OSCALE, bj1), 0.0f) * ASCALE);
                    a_store(sm, r1, j,
                            fmaxf(fmaf(acc[s][t][2], OSCALE, bj0), 0.0f) * ASCALE,
                            fmaxf(fmaf(acc[s][t][3], OSCALE, bj1), 0.0f) * ASCALE);
                }
            }
            {   // tile 12: rows of subtile s = wc, global cols 96..103
                const int r0 = wr * 32 + wc * 16 + (lane >> 2);
                const int r1 = r0 + 8;
                int j = 96 + 2 * (lane & 3);
                float bj0 = bias[j], bj1 = bias[j + 1];
                a_store(sm, r0, j,
                        fmaxf(fmaf(acc12[0], OSCALE, bj0), 0.0f) * ASCALE,
                        fmaxf(fmaf(acc12[1], OSCALE, bj1), 0.0f) * ASCALE);
                a_store(sm, r1, j,
                        fmaxf(fmaf(acc12[2], OSCALE, bj0), 0.0f) * ASCALE,
                        fmaxf(fmaf(acc12[3], OSCALE, bj1), 0.0f) * ASCALE);
            }
            // warp-private rows: no barrier needed (next chunk barrier orders B)
        } else {
            // final: relu(acc*OSCALE + b6) dot W7 -> reduce -> sigmoid
            const float* bias = p.b[6];
            const float* W7   = p.W[7];
            float* red = (float*)(sm + SM_B);   // <=1KB inside drained slot 0
            #pragma unroll
            for (int s = 0; s < 2; ++s) {
                const int r0 = wr * 32 + s * 16 + (lane >> 2);
                const int r1 = r0 + 8;
                float p0 = 0.0f, p1 = 0.0f;
                #pragma unroll
                for (int t = 0; t < 12; ++t) {
                    int j = wc * 104 + t * 8 + 2 * (lane & 3);
                    float bj0 = bias[j], w0 = W7[j];
                    float bj1 = bias[j + 1], w1 = W7[j + 1];
                    p0 = fmaf(fmaxf(fmaf(acc[s][t][0], OSCALE, bj0), 0.0f), w0, p0);
                    p0 = fmaf(fmaxf(fmaf(acc[s][t][1], OSCALE, bj1), 0.0f), w1, p0);
                    p1 = fmaf(fmaxf(fmaf(acc[s][t][2], OSCALE, bj0), 0.0f), w0, p1);
                    p1 = fmaf(fmaxf(fmaf(acc[s][t][3], OSCALE, bj1), 0.0f), w1, p1);
                }
                if (s == wc) {   // tile 12 contribution
                    int j = 96 + 2 * (lane & 3);
                    float bj0 = bias[j], w0 = W7[j];
                    float bj1 = bias[j + 1], w1 = W7[j + 1];
                    p0 = fmaf(fmaxf(fmaf(acc12[0], OSCALE, bj0), 0.0f), w0, p0);
                    p0 = fmaf(fmaxf(fmaf(acc12[1], OSCALE, bj1), 0.0f), w1, p0);
                    p1 = fmaf(fmaxf(fmaf(acc12[2], OSCALE, bj0), 0.0f), w0, p1);
                    p1 = fmaf(fmaxf(fmaf(acc12[3], OSCALE, bj1), 0.0f), w1, p1);
                }
                p0 += __shfl_xor_sync(0xffffffff, p0, 1);
                p0 += __shfl_xor_sync(0xffffffff, p0, 2);
                p1 += __shfl_xor_sync(0xffffffff, p1, 1);
                p1 += __shfl_xor_sync(0xffffffff, p1, 2);
                if ((lane & 3) == 0) {
                    red[r0 * 2 + wc] = p0;
                    red[r1 * 2 + wc] = p1;
                }
            }
            __syncthreads();
            if (tid < MT) {
                float s = red[tid * 2] + red[tid * 2 + 1] + p.b[7][0];
                out[row0 + tid] = 1.0f / (1.0f + expf(-s));
            }
        }
    }
}

// ---------------------------------------------------------------------------
extern "C" void kernel_launch(void* const* d_in, const int* in_sizes, int n_in,
                              void* d_out, int out_size) {
    const float* x  = (const float*)d_in[0];
    const void*  ei = d_in[1];
    Params p;
    for (int i = 0; i < 8; ++i) {
        p.W[i] = (const float*)d_in[2 + 2 * i];
        p.b[i] = (const float*)d_in[3 + 2 * i];
    }
    float* out = (float*)d_out;

    cudaFuncSetAttribute(mlp_kernel, cudaFuncAttributeMaxDynamicSharedMemorySize, SMEM_BYTES);

    detect_kernel<<<1, 32>>>((const int*)ei);
    prep_w_kernel<<<(6 * NCHK * BNR * BKP + 255) / 256, 256>>>(p);
    zero_deg_kernel<<<NN / 256, 256>>>();
    deg_kernel<<<2048, 256>>>(ei);
    inv_init_kernel<<<NN / 256, 256>>>(x);
    edge_agg_kernel<<<2048, 256>>>(x, ei);
    mlp_kernel<<<NN / MT, THREADS, SMEM_BYTES>>>(p, out);
}